// round 11
// baseline (speedup 1.0000x reference)
#include <cuda_runtime.h>
#include <cuda_bf16.h>

// Problem constants (fixed dataset: B=2048, C=9605, top-k=10)
#define NB      2048
#define NC      9605
#define TOPK    10
#define CAP     256
#define NT      256
#define THRESH  2.3f   // ~103 candidates/row expected; fallback covers <10 or >CAP

// Scratch (no allocations allowed)
__device__ float g_rowfinal[NB];
__device__ int   g_done = 0;

__device__ __forceinline__ float rcp_fast(float a) {
    float r; asm("rcp.approx.f32 %0, %1;" : "=f"(r) : "f"(a)); return r;
}

__device__ __forceinline__ unsigned long long umax64(unsigned long long a, unsigned long long b) {
    return a > b ? a : b;
}

// base*w for one element.
// y=0: base=log(min(1-p+0.05,1)), w=(1-xs_neg)^4 = max(p-0.05,0)^4
// y=1: base=log(max(p,eps)),      w=(1-p)
__device__ __forceinline__ float term_val(float xv, float yv) {
    float t   = __expf(-xv);           // FMUL + MUFU.EX2
    float sig = rcp_fast(1.0f + t);    // FADD + MUFU.RCP
    float u   = fmaxf(sig - 0.05f, 0.0f);
    float u2  = u * u;
    bool  pos = yv > 0.5f;
    float larg = pos ? fmaxf(sig, 1e-8f) : (1.05f - sig);
    float wmul = pos ? (1.0f - sig)      : (u2 * u2);
    return __logf(larg) * wmul;        // MUFU.LG2 + FMUL
}

// ordered-uint key for full-range float (fallback path)
__device__ __forceinline__ unsigned orderf(float v) {
    unsigned b = __float_as_uint(v);
    return (b & 0x80000000u) ? ~b : (b | 0x80000000u);
}

__global__ void __launch_bounds__(NT, 8)   // force 8 blocks/SM -> 64 warps (occ 100%)
loss_main_kernel(const float* __restrict__ x, const float* __restrict__ y,
                 const int* __restrict__ ci, int n1,
                 const int* __restrict__ ri, int n2,
                 const int* __restrict__ di, int n3,
                 const int* __restrict__ wl_map,
                 float* __restrict__ out)
{
    __shared__ float              s_val[CAP];
    __shared__ int                s_idx[CAP];
    __shared__ unsigned long long s_key[CAP];
    __shared__ unsigned long long s_wkey[NT / 32];
    __shared__ float              s_wsum[NT / 32];
    __shared__ unsigned long long s_kmax;
    __shared__ int                s_cnt;
    __shared__ int                s_flags;
    __shared__ int                s_sel[TOPK];
    __shared__ int                s_wl[TOPK];
    __shared__ float              s_term[TOPK];
    __shared__ float              s_rowsum;
    __shared__ int                s_islast;

    const int row  = blockIdx.x;
    const int tid  = threadIdx.x;
    const int lane = tid & 31;
    const int wid  = tid >> 5;

    if (tid == 0) { s_cnt = 0; s_flags = 0; }
    __syncthreads();

    const float* __restrict__ xr = x + (size_t)row * NC;
    const float* __restrict__ yr = y + (size_t)row * NC;

    // ---- streaming pass: scalar loads, divergent rare push ----
    float acc = 0.0f;
    #pragma unroll 4
    for (int j = tid; j < NC; j += NT) {
        float xv = xr[j];
        float yv = yr[j];
        acc += term_val(xv, yv);
        if (xv > THRESH) {
            int p = atomicAdd(&s_cnt, 1);
            if (p < CAP) { s_val[p] = xv; s_idx[p] = j; }
        }
    }

    // ---- ground-truth whitelist flags (y at the three index lists) ----
    int ntot = n1 + n2 + n3;
    for (int t = tid; t < ntot; t += NT) {
        int cls, bit;
        if (t < n1)           { cls = ci[t];           bit = 1; }
        else if (t < n1 + n2) { cls = ri[t - n1];      bit = 2; }
        else                  { cls = di[t - n1 - n2]; bit = 4; }
        if (yr[cls] > 0.5f) atomicOr(&s_flags, bit);
    }

    // ---- row sum reduction ----
    #pragma unroll
    for (int o = 16; o > 0; o >>= 1) acc += __shfl_down_sync(0xFFFFFFFFu, acc, o);
    if (lane == 0) s_wsum[wid] = acc;
    __syncthreads();
    if (tid == 0) {
        float s = 0.0f;
        #pragma unroll
        for (int i = 0; i < NT / 32; i++) s += s_wsum[i];
        s_rowsum = s;
    }

    int cntraw = s_cnt;                 // valid after the sync above
    int cnt    = min(cntraw, CAP);
    bool fast  = (cntraw >= TOPK) && (cntraw <= CAP);

    if (fast) {
        // key: [val bits | ~idx]  -> larger val wins, tie -> smaller idx wins
        unsigned long long mykey = 0ull;
        if (tid < cnt)
            mykey = ((unsigned long long)__float_as_uint(s_val[tid]) << 32)
                  | (unsigned long long)(unsigned)(~s_idx[tid]);
        s_key[tid] = mykey;
        __syncthreads();

        for (int r = 0; r < TOPK; r++) {
            unsigned long long k = s_key[tid];
            #pragma unroll
            for (int o = 16; o > 0; o >>= 1)
                k = umax64(k, __shfl_down_sync(0xFFFFFFFFu, k, o));
            if (lane == 0) s_wkey[wid] = k;
            __syncthreads();
            if (tid == 0) {
                unsigned long long m = s_wkey[0];
                #pragma unroll
                for (int i = 1; i < NT / 32; i++) m = umax64(m, s_wkey[i]);
                s_kmax = m;
                s_sel[r] = (int)(~(unsigned)m);
            }
            __syncthreads();
            if (s_key[tid] == s_kmax) s_key[tid] = 0ull;  // winner drops out
            __syncthreads();
        }
    } else {
        // exact (never expected on this data): 10 block-argmax rounds over full row
        for (int r = 0; r < TOPK; r++) {
            unsigned long long best = 0ull;
            for (int j = tid; j < NC; j += NT) {
                bool taken = false;
                for (int q = 0; q < r; q++) if (s_sel[q] == j) taken = true;
                if (!taken) {
                    unsigned long long key =
                        ((unsigned long long)orderf(xr[j]) << 32)
                      | (unsigned long long)(unsigned)(~j);
                    best = umax64(best, key);
                }
            }
            #pragma unroll
            for (int o = 16; o > 0; o >>= 1)
                best = umax64(best, __shfl_down_sync(0xFFFFFFFFu, best, o));
            if (lane == 0) s_wkey[wid] = best;
            __syncthreads();
            if (tid == 0) {
                unsigned long long m = s_wkey[0];
                #pragma unroll
                for (int i = 1; i < NT / 32; i++) m = umax64(m, s_wkey[i]);
                s_sel[r] = (int)(~(unsigned)m);
            }
            __syncthreads();
        }
    }

    // ---- in-block finalize: wl_map gathers + recomputed terms for top-10 ----
    if (tid < TOPK) {
        int j = s_sel[tid];
        s_wl[tid]   = wl_map[j];                 // L2-resident
        s_term[tid] = term_val(xr[j], yr[j]);    // L1/L2-hot
    }
    __syncthreads();

    if (tid == 0) {
        int  flags = s_flags;
        bool has1  = (flags & 1) != 0;
        bool has2  = (flags & 2) != 0;
        bool has3  = (flags & 4) != 0;
        bool gt4   = !(has1 || has2 || has3);

        float fm[TOPK];
        bool  found = false;
        #pragma unroll
        for (int r = 0; r < TOPK; r++) {
            int  wl     = s_wl[r];
            bool in_map = wl > 0;
            bool in_gt  = ((wl == 1) && has1) || ((wl == 2) && has2) ||
                          ((wl == 3) && has3) || ((wl == 4) && gt4);
            float f = (in_map && gt4) ? 0.5f : 1.0f;
            if (in_map && !in_gt && !found) f *= 2.0f;
            fm[r] = f;
            found = found || (in_map && in_gt);
        }
        float extra = found ? 1.0f : 2.0f;

        float corr = 0.0f;
        #pragma unroll
        for (int r = 0; r < TOPK; r++) {
            float m = fm[r] * extra;
            corr += (m - 1.0f) * s_term[r];      // zero when m==1
        }
        g_rowfinal[row] = s_rowsum + corr;
        __threadfence();
        int t = atomicAdd(&g_done, 1);
        s_islast = (t == NB - 1) ? 1 : 0;
    }
    __syncthreads();

    // ---- last block performs the deterministic final reduction ----
    if (s_islast) {
        __threadfence();                        // acquire: all g_rowfinal visible
        float part = 0.0f;
        #pragma unroll
        for (int i = tid; i < NB; i += NT) part += g_rowfinal[i];
        #pragma unroll
        for (int o = 16; o > 0; o >>= 1) part += __shfl_down_sync(0xFFFFFFFFu, part, o);
        if (lane == 0) s_wsum[wid] = part;
        __syncthreads();
        if (tid == 0) {
            float s = 0.0f;
            #pragma unroll
            for (int i = 0; i < NT / 32; i++) s += s_wsum[i];
            out[0] = -s;
            atomicExch(&g_done, 0);             // reset for next graph replay
        }
    }
}

extern "C" void kernel_launch(void* const* d_in, const int* in_sizes, int n_in,
                              void* d_out, int out_size)
{
    const float* x  = (const float*)d_in[0];
    const float* y  = (const float*)d_in[1];
    const int*   ci = (const int*)d_in[2];
    const int*   ri = (const int*)d_in[3];
    const int*   di = (const int*)d_in[4];
    const int*   wl = (const int*)d_in[5];
    int n1 = in_sizes[2], n2 = in_sizes[3], n3 = in_sizes[4];
    float* out = (float*)d_out;

    loss_main_kernel<<<NB, NT>>>(x, y, ci, n1, ri, n2, di, n3, wl, out);
}

// round 12
// speedup vs baseline: 1.3345x; 1.3345x over previous
#include <cuda_runtime.h>
#include <cuda_bf16.h>

// Problem constants (fixed dataset: B=2048, C=9605, top-k=10)
#define NB      2048
#define NC      9605
#define TOPK    10
#define CAP     256
#define NT      256
#define THRESH  2.3f   // ~103 candidates/row expected; fallback covers <10 or >CAP
#define LN2F    0.69314718055994531f

// Scratch (no allocations allowed)
__device__ float g_rowfinal[NB];
__device__ int   g_done = 0;

__device__ __forceinline__ float rcp_fast(float a) {
    float r; asm("rcp.approx.f32 %0, %1;" : "=f"(r) : "f"(a)); return r;
}

__device__ __forceinline__ unsigned long long umax64(unsigned long long a, unsigned long long b) {
    return a > b ? a : b;
}

// base*w for one element, in log2 units (row sums scaled by LN2F once).
// y=0: lg2(min(1-p+0.05,1)) * max(p-0.05,0)^4
// y=1: lg2(max(p,eps))      * (1-p)
__device__ __forceinline__ float term_lg2(float xv, float yv) {
    float t   = __expf(-xv);           // FMUL + MUFU.EX2
    float sig = rcp_fast(1.0f + t);    // FADD + MUFU.RCP
    float u   = fmaxf(sig - 0.05f, 0.0f);
    float u2  = u * u;
    bool  pos = yv > 0.5f;
    float larg = pos ? fmaxf(sig, 1e-8f) : (1.05f - sig);
    float wmul = pos ? (1.0f - sig)      : (u2 * u2);
    return __log2f(larg) * wmul;       // MUFU.LG2 + FMUL (no ln2 FMUL)
}

// ordered-uint key for full-range float (fallback path)
__device__ __forceinline__ unsigned orderf(float v) {
    unsigned b = __float_as_uint(v);
    return (b & 0x80000000u) ? ~b : (b | 0x80000000u);
}

__global__ void __launch_bounds__(NT)
loss_main_kernel(const float* __restrict__ x, const float* __restrict__ y,
                 const int* __restrict__ ci, int n1,
                 const int* __restrict__ ri, int n2,
                 const int* __restrict__ di, int n3,
                 const int* __restrict__ wl_map,
                 float* __restrict__ out)
{
    __shared__ float              s_val[CAP];
    __shared__ int                s_idx[CAP];
    __shared__ unsigned long long s_key[CAP];
    __shared__ unsigned long long s_wkey[NT / 32];
    __shared__ float              s_wsum[NT / 32];
    __shared__ unsigned long long s_kmax;
    __shared__ int                s_cnt;
    __shared__ int                s_flags;
    __shared__ int                s_sel[TOPK];
    __shared__ int                s_wl[TOPK];
    __shared__ float              s_term[TOPK];
    __shared__ float              s_rowsum;
    __shared__ int                s_islast;

    const int row  = blockIdx.x;
    const int tid  = threadIdx.x;
    const int lane = tid & 31;
    const int wid  = tid >> 5;

    if (tid == 0) { s_cnt = 0; s_flags = 0; }
    __syncthreads();

    const float* __restrict__ xr = x + (size_t)row * NC;
    const float* __restrict__ yr = y + (size_t)row * NC;

    // ---- R2 streaming pass (measured fastest): aligned float4, divergent push ----
    float acc = 0.0f;

    // prologue: bring row pointer to 16B alignment (row stride 9605 ≡ 1 mod 4)
    const int prol = (4 - (row & 3)) & 3;       // 0..3 scalar elems
    if (tid < prol) {
        float xv = xr[tid];
        float yv = yr[tid];
        acc += term_lg2(xv, yv);
        if (xv > THRESH) {
            int p = atomicAdd(&s_cnt, 1);
            if (p < CAP) { s_val[p] = xv; s_idx[p] = tid; }
        }
    }

    const int nrem = NC - prol;
    const int nvec = nrem >> 2;                  // float4 count
    const float4* __restrict__ x4 = (const float4*)(xr + prol);
    const float4* __restrict__ y4 = (const float4*)(yr + prol);

    for (int v = tid; v < nvec; v += NT) {
        float4 xv = x4[v];
        float4 yv = y4[v];
        int base = prol + (v << 2);
        acc += term_lg2(xv.x, yv.x);
        acc += term_lg2(xv.y, yv.y);
        acc += term_lg2(xv.z, yv.z);
        acc += term_lg2(xv.w, yv.w);
        if (xv.x > THRESH) { int p = atomicAdd(&s_cnt, 1); if (p < CAP) { s_val[p] = xv.x; s_idx[p] = base + 0; } }
        if (xv.y > THRESH) { int p = atomicAdd(&s_cnt, 1); if (p < CAP) { s_val[p] = xv.y; s_idx[p] = base + 1; } }
        if (xv.z > THRESH) { int p = atomicAdd(&s_cnt, 1); if (p < CAP) { s_val[p] = xv.z; s_idx[p] = base + 2; } }
        if (xv.w > THRESH) { int p = atomicAdd(&s_cnt, 1); if (p < CAP) { s_val[p] = xv.w; s_idx[p] = base + 3; } }
    }

    // tail (0..3 scalar elems)
    for (int j = prol + (nvec << 2) + tid; j < NC; j += NT) {
        float xv = xr[j];
        float yv = yr[j];
        acc += term_lg2(xv, yv);
        if (xv > THRESH) {
            int p = atomicAdd(&s_cnt, 1);
            if (p < CAP) { s_val[p] = xv; s_idx[p] = j; }
        }
    }

    // ---- ground-truth whitelist flags (y at the three index lists) ----
    int ntot = n1 + n2 + n3;
    for (int t = tid; t < ntot; t += NT) {
        int cls, bit;
        if (t < n1)           { cls = ci[t];           bit = 1; }
        else if (t < n1 + n2) { cls = ri[t - n1];      bit = 2; }
        else                  { cls = di[t - n1 - n2]; bit = 4; }
        if (yr[cls] > 0.5f) atomicOr(&s_flags, bit);
    }

    // ---- row sum reduction ----
    #pragma unroll
    for (int o = 16; o > 0; o >>= 1) acc += __shfl_down_sync(0xFFFFFFFFu, acc, o);
    if (lane == 0) s_wsum[wid] = acc;
    __syncthreads();
    if (tid == 0) {
        float s = 0.0f;
        #pragma unroll
        for (int i = 0; i < NT / 32; i++) s += s_wsum[i];
        s_rowsum = s;
    }

    int cntraw = s_cnt;                 // valid after the sync above
    int cnt    = min(cntraw, CAP);
    bool fast  = (cntraw >= TOPK) && (cntraw <= CAP);

    if (fast) {
        // key: [val bits | ~idx]  -> larger val wins, tie -> smaller idx wins
        unsigned long long mykey = 0ull;
        if (tid < cnt)
            mykey = ((unsigned long long)__float_as_uint(s_val[tid]) << 32)
                  | (unsigned long long)(unsigned)(~s_idx[tid]);
        s_key[tid] = mykey;
        __syncthreads();

        for (int r = 0; r < TOPK; r++) {
            unsigned long long k = s_key[tid];
            #pragma unroll
            for (int o = 16; o > 0; o >>= 1)
                k = umax64(k, __shfl_down_sync(0xFFFFFFFFu, k, o));
            if (lane == 0) s_wkey[wid] = k;
            __syncthreads();
            if (tid == 0) {
                unsigned long long m = s_wkey[0];
                #pragma unroll
                for (int i = 1; i < NT / 32; i++) m = umax64(m, s_wkey[i]);
                s_kmax = m;
                s_sel[r] = (int)(~(unsigned)m);
            }
            __syncthreads();
            if (s_key[tid] == s_kmax) s_key[tid] = 0ull;  // winner drops out
            __syncthreads();
        }
    } else {
        // exact (never expected on this data): 10 block-argmax rounds over full row
        for (int r = 0; r < TOPK; r++) {
            unsigned long long best = 0ull;
            for (int j = tid; j < NC; j += NT) {
                bool taken = false;
                for (int q = 0; q < r; q++) if (s_sel[q] == j) taken = true;
                if (!taken) {
                    unsigned long long key =
                        ((unsigned long long)orderf(xr[j]) << 32)
                      | (unsigned long long)(unsigned)(~j);
                    best = umax64(best, key);
                }
            }
            #pragma unroll
            for (int o = 16; o > 0; o >>= 1)
                best = umax64(best, __shfl_down_sync(0xFFFFFFFFu, best, o));
            if (lane == 0) s_wkey[wid] = best;
            __syncthreads();
            if (tid == 0) {
                unsigned long long m = s_wkey[0];
                #pragma unroll
                for (int i = 1; i < NT / 32; i++) m = umax64(m, s_wkey[i]);
                s_sel[r] = (int)(~(unsigned)m);
            }
            __syncthreads();
        }
    }

    // ---- in-block finalize: wl_map gathers + recomputed terms for top-10 ----
    if (tid < TOPK) {
        int j = s_sel[tid];
        s_wl[tid]   = wl_map[j];                 // L2-resident
        s_term[tid] = term_lg2(xr[j], yr[j]);    // L1/L2-hot, log2 units
    }
    __syncthreads();

    if (tid == 0) {
        int  flags = s_flags;
        bool has1  = (flags & 1) != 0;
        bool has2  = (flags & 2) != 0;
        bool has3  = (flags & 4) != 0;
        bool gt4   = !(has1 || has2 || has3);

        float fm[TOPK];
        bool  found = false;
        #pragma unroll
        for (int r = 0; r < TOPK; r++) {
            int  wl     = s_wl[r];
            bool in_map = wl > 0;
            bool in_gt  = ((wl == 1) && has1) || ((wl == 2) && has2) ||
                          ((wl == 3) && has3) || ((wl == 4) && gt4);
            float f = (in_map && gt4) ? 0.5f : 1.0f;
            if (in_map && !in_gt && !found) f *= 2.0f;
            fm[r] = f;
            found = found || (in_map && in_gt);
        }
        float extra = found ? 1.0f : 2.0f;

        float corr = 0.0f;
        #pragma unroll
        for (int r = 0; r < TOPK; r++) {
            float m = fm[r] * extra;
            corr += (m - 1.0f) * s_term[r];      // zero when m==1
        }
        g_rowfinal[row] = (s_rowsum + corr) * LN2F;   // log2 -> natural units
        __threadfence();
        int t = atomicAdd(&g_done, 1);
        s_islast = (t == NB - 1) ? 1 : 0;
    }
    __syncthreads();

    // ---- last block performs the deterministic final reduction ----
    if (s_islast) {
        __threadfence();                        // acquire: all g_rowfinal visible
        float part = 0.0f;
        #pragma unroll
        for (int i = tid; i < NB; i += NT) part += g_rowfinal[i];
        #pragma unroll
        for (int o = 16; o > 0; o >>= 1) part += __shfl_down_sync(0xFFFFFFFFu, part, o);
        if (lane == 0) s_wsum[wid] = part;
        __syncthreads();
        if (tid == 0) {
            float s = 0.0f;
            #pragma unroll
            for (int i = 0; i < NT / 32; i++) s += s_wsum[i];
            out[0] = -s;
            atomicExch(&g_done, 0);             // reset for next graph replay
        }
    }
}

extern "C" void kernel_launch(void* const* d_in, const int* in_sizes, int n_in,
                              void* d_out, int out_size)
{
    const float* x  = (const float*)d_in[0];
    const float* y  = (const float*)d_in[1];
    const int*   ci = (const int*)d_in[2];
    const int*   ri = (const int*)d_in[3];
    const int*   di = (const int*)d_in[4];
    const int*   wl = (const int*)d_in[5];
    int n1 = in_sizes[2], n2 = in_sizes[3], n3 = in_sizes[4];
    float* out = (float*)d_out;

    loss_main_kernel<<<NB, NT>>>(x, y, ci, n1, ri, n2, di, n3, wl, out);
}

// round 13
// speedup vs baseline: 1.4830x; 1.1113x over previous
#include <cuda_runtime.h>
#include <cuda_bf16.h>

// Problem constants (fixed dataset: B=2048, C=9605, top-k=10)
#define NB      2048
#define NC      9605
#define TOPK    10
#define CAP     256
#define NT      256
#define THRESH  2.3f   // ~103 candidates/row expected; fallback covers <10 or >CAP
#define LN2F    0.69314718055994531f

// Scratch (no allocations allowed)
__device__ float g_rowfinal[NB];
__device__ int   g_done = 0;

__device__ __forceinline__ float rcp_fast(float a) {
    float r; asm("rcp.approx.f32 %0, %1;" : "=f"(r) : "f"(a)); return r;
}

__device__ __forceinline__ unsigned long long umax64(unsigned long long a, unsigned long long b) {
    return a > b ? a : b;
}

// base*w for one element, in log2 units (row sums scaled by LN2F once).
__device__ __forceinline__ float term_lg2(float xv, float yv) {
    float t   = __expf(-xv);           // FMUL + MUFU.EX2
    float sig = rcp_fast(1.0f + t);    // FADD + MUFU.RCP
    float u   = fmaxf(sig - 0.05f, 0.0f);
    float u2  = u * u;
    bool  pos = yv > 0.5f;
    float larg = pos ? fmaxf(sig, 1e-8f) : (1.05f - sig);
    float wmul = pos ? (1.0f - sig)      : (u2 * u2);
    return __log2f(larg) * wmul;       // MUFU.LG2 + FMUL
}

// ordered-uint key for full-range float (fallback path)
__device__ __forceinline__ unsigned orderf(float v) {
    unsigned b = __float_as_uint(v);
    return (b & 0x80000000u) ? ~b : (b | 0x80000000u);
}

__global__ void __launch_bounds__(NT)
loss_main_kernel(const float* __restrict__ x, const float* __restrict__ y,
                 const int* __restrict__ ci, int n1,
                 const int* __restrict__ ri, int n2,
                 const int* __restrict__ di, int n3,
                 const int* __restrict__ wl_map,
                 float* __restrict__ out)
{
    __shared__ float              s_val[CAP];
    __shared__ int                s_idx[CAP];
    __shared__ unsigned long long s_wkey[NT / 32];
    __shared__ float              s_wsum[NT / 32];
    __shared__ int                s_cnt;
    __shared__ int                s_flags;
    __shared__ int                s_sel[TOPK];
    __shared__ int                s_wl[TOPK];
    __shared__ float              s_term[TOPK];
    __shared__ int                s_islast;

    const int row  = blockIdx.x;
    const int tid  = threadIdx.x;
    const int lane = tid & 31;
    const int wid  = tid >> 5;

    if (tid == 0) { s_cnt = 0; s_flags = 0; }
    __syncthreads();

    const float* __restrict__ xr = x + (size_t)row * NC;
    const float* __restrict__ yr = y + (size_t)row * NC;

    // ---- streaming pass (R2/R11 form, measured fastest): float4, divergent push ----
    float acc = 0.0f;

    const int prol = (4 - (row & 3)) & 3;       // 0..3 scalar elems to 16B-align
    if (tid < prol) {
        float xv = xr[tid];
        float yv = yr[tid];
        acc += term_lg2(xv, yv);
        if (xv > THRESH) {
            int p = atomicAdd(&s_cnt, 1);
            if (p < CAP) { s_val[p] = xv; s_idx[p] = tid; }
        }
    }

    const int nrem = NC - prol;
    const int nvec = nrem >> 2;
    const float4* __restrict__ x4 = (const float4*)(xr + prol);
    const float4* __restrict__ y4 = (const float4*)(yr + prol);

    for (int v = tid; v < nvec; v += NT) {
        float4 xv = x4[v];
        float4 yv = y4[v];
        int base = prol + (v << 2);
        acc += term_lg2(xv.x, yv.x);
        acc += term_lg2(xv.y, yv.y);
        acc += term_lg2(xv.z, yv.z);
        acc += term_lg2(xv.w, yv.w);
        if (xv.x > THRESH) { int p = atomicAdd(&s_cnt, 1); if (p < CAP) { s_val[p] = xv.x; s_idx[p] = base + 0; } }
        if (xv.y > THRESH) { int p = atomicAdd(&s_cnt, 1); if (p < CAP) { s_val[p] = xv.y; s_idx[p] = base + 1; } }
        if (xv.z > THRESH) { int p = atomicAdd(&s_cnt, 1); if (p < CAP) { s_val[p] = xv.z; s_idx[p] = base + 2; } }
        if (xv.w > THRESH) { int p = atomicAdd(&s_cnt, 1); if (p < CAP) { s_val[p] = xv.w; s_idx[p] = base + 3; } }
    }

    for (int j = prol + (nvec << 2) + tid; j < NC; j += NT) {
        float xv = xr[j];
        float yv = yr[j];
        acc += term_lg2(xv, yv);
        if (xv > THRESH) {
            int p = atomicAdd(&s_cnt, 1);
            if (p < CAP) { s_val[p] = xv; s_idx[p] = j; }
        }
    }

    // ---- ground-truth whitelist flags ----
    int ntot = n1 + n2 + n3;
    for (int t = tid; t < ntot; t += NT) {
        int cls, bit;
        if (t < n1)           { cls = ci[t];           bit = 1; }
        else if (t < n1 + n2) { cls = ri[t - n1];      bit = 2; }
        else                  { cls = di[t - n1 - n2]; bit = 4; }
        if (yr[cls] > 0.5f) atomicOr(&s_flags, bit);
    }

    // ---- per-warp partial row sums ----
    #pragma unroll
    for (int o = 16; o > 0; o >>= 1) acc += __shfl_down_sync(0xFFFFFFFFu, acc, o);
    if (lane == 0) s_wsum[wid] = acc;

    __syncthreads();   // lists, flags, partial sums all final

    int  cntraw = s_cnt;
    bool fast   = (cntraw >= TOPK) && (cntraw <= CAP);   // block-uniform

    if (fast) {
        // ==== warp-0-only, barrier-free top-k + finalize ====
        if (wid == 0) {
            // 8 candidate keys per lane, register-resident
            unsigned long long k[8];
            #pragma unroll
            for (int i = 0; i < 8; i++) {
                int p = lane + (i << 5);
                k[i] = (p < cntraw)
                     ? (((unsigned long long)__float_as_uint(s_val[p]) << 32)
                        | (unsigned long long)(unsigned)(~s_idx[p]))
                     : 0ull;
            }
            // 10 rounds of warp argmax; lane r keeps the r-th winner index
            int myj = 0;
            #pragma unroll
            for (int r = 0; r < TOPK; r++) {
                unsigned long long m = k[0];
                #pragma unroll
                for (int i = 1; i < 8; i++) m = umax64(m, k[i]);
                #pragma unroll
                for (int o = 16; o > 0; o >>= 1)
                    m = umax64(m, __shfl_xor_sync(0xFFFFFFFFu, m, o));  // all-reduce
                if (lane == r) myj = (int)(~(unsigned)m);
                #pragma unroll
                for (int i = 0; i < 8; i++) if (k[i] == m) k[i] = 0ull; // unique key
            }
            // lanes 0..9: gather wl + recompute term (parallel)
            int   mywl   = 0;
            float myterm = 0.0f;
            if (lane < TOPK) {
                mywl   = wl_map[myj];
                myterm = term_lg2(xr[myj], yr[myj]);
            }
            // sequential multiplier logic (all lanes compute; lane 0's result used)
            int  flags = s_flags;
            bool has1  = (flags & 1) != 0;
            bool has2  = (flags & 2) != 0;
            bool has3  = (flags & 4) != 0;
            bool gt4   = !(has1 || has2 || has3);

            float corr  = 0.0f;
            bool  found = false;
            float fmr[TOPK];
            float tvr[TOPK];
            #pragma unroll
            for (int r = 0; r < TOPK; r++) {
                int   wl = __shfl_sync(0xFFFFFFFFu, mywl,   r);
                float tv = __shfl_sync(0xFFFFFFFFu, myterm, r);
                bool in_map = wl > 0;
                bool in_gt  = ((wl == 1) && has1) || ((wl == 2) && has2) ||
                              ((wl == 3) && has3) || ((wl == 4) && gt4);
                float f = (in_map && gt4) ? 0.5f : 1.0f;
                if (in_map && !in_gt && !found) f *= 2.0f;
                fmr[r] = f;
                tvr[r] = tv;
                found  = found || (in_map && in_gt);
            }
            float extra = found ? 1.0f : 2.0f;
            #pragma unroll
            for (int r = 0; r < TOPK; r++)
                corr += (fmr[r] * extra - 1.0f) * tvr[r];

            if (lane == 0) {
                float s = 0.0f;
                #pragma unroll
                for (int i = 0; i < NT / 32; i++) s += s_wsum[i];
                g_rowfinal[row] = (s + corr) * LN2F;
                __threadfence();
                int t = atomicAdd(&g_done, 1);
                s_islast = (t == NB - 1) ? 1 : 0;
            }
        }
    } else {
        // ==== exact fallback (block-uniform branch; never expected) ====
        for (int r = 0; r < TOPK; r++) {
            unsigned long long best = 0ull;
            for (int j = tid; j < NC; j += NT) {
                bool taken = false;
                for (int q = 0; q < r; q++) if (s_sel[q] == j) taken = true;
                if (!taken) {
                    unsigned long long key =
                        ((unsigned long long)orderf(xr[j]) << 32)
                      | (unsigned long long)(unsigned)(~j);
                    best = umax64(best, key);
                }
            }
            #pragma unroll
            for (int o = 16; o > 0; o >>= 1)
                best = umax64(best, __shfl_down_sync(0xFFFFFFFFu, best, o));
            if (lane == 0) s_wkey[wid] = best;
            __syncthreads();
            if (tid == 0) {
                unsigned long long m = s_wkey[0];
                #pragma unroll
                for (int i = 1; i < NT / 32; i++) m = umax64(m, s_wkey[i]);
                s_sel[r] = (int)(~(unsigned)m);
            }
            __syncthreads();
        }
        if (tid < TOPK) {
            int j = s_sel[tid];
            s_wl[tid]   = wl_map[j];
            s_term[tid] = term_lg2(xr[j], yr[j]);
        }
        __syncthreads();
        if (tid == 0) {
            int  flags = s_flags;
            bool has1  = (flags & 1) != 0;
            bool has2  = (flags & 2) != 0;
            bool has3  = (flags & 4) != 0;
            bool gt4   = !(has1 || has2 || has3);

            float fm[TOPK];
            bool  found = false;
            #pragma unroll
            for (int r = 0; r < TOPK; r++) {
                int  wl     = s_wl[r];
                bool in_map = wl > 0;
                bool in_gt  = ((wl == 1) && has1) || ((wl == 2) && has2) ||
                              ((wl == 3) && has3) || ((wl == 4) && gt4);
                float f = (in_map && gt4) ? 0.5f : 1.0f;
                if (in_map && !in_gt && !found) f *= 2.0f;
                fm[r] = f;
                found = found || (in_map && in_gt);
            }
            float extra = found ? 1.0f : 2.0f;

            float corr = 0.0f;
            #pragma unroll
            for (int r = 0; r < TOPK; r++)
                corr += (fm[r] * extra - 1.0f) * s_term[r];

            float s = 0.0f;
            #pragma unroll
            for (int i = 0; i < NT / 32; i++) s += s_wsum[i];
            g_rowfinal[row] = (s + corr) * LN2F;
            __threadfence();
            int t = atomicAdd(&g_done, 1);
            s_islast = (t == NB - 1) ? 1 : 0;
        }
    }

    __syncthreads();   // s_islast visible to all

    // ---- last block performs the deterministic final reduction ----
    if (s_islast) {
        __threadfence();                        // acquire: all g_rowfinal visible
        float part = 0.0f;
        #pragma unroll
        for (int i = tid; i < NB; i += NT) part += g_rowfinal[i];
        #pragma unroll
        for (int o = 16; o > 0; o >>= 1) part += __shfl_down_sync(0xFFFFFFFFu, part, o);
        if (lane == 0) s_wsum[wid] = part;
        __syncthreads();
        if (tid == 0) {
            float s = 0.0f;
            #pragma unroll
            for (int i = 0; i < NT / 32; i++) s += s_wsum[i];
            out[0] = -s;
            atomicExch(&g_done, 0);             // reset for next graph replay
        }
    }
}

extern "C" void kernel_launch(void* const* d_in, const int* in_sizes, int n_in,
                              void* d_out, int out_size)
{
    const float* x  = (const float*)d_in[0];
    const float* y  = (const float*)d_in[1];
    const int*   ci = (const int*)d_in[2];
    const int*   ri = (const int*)d_in[3];
    const int*   di = (const int*)d_in[4];
    const int*   wl = (const int*)d_in[5];
    int n1 = in_sizes[2], n2 = in_sizes[3], n3 = in_sizes[4];
    float* out = (float*)d_out;

    loss_main_kernel<<<NB, NT>>>(x, y, ci, n1, ri, n2, di, n3, wl, out);
}